// round 3
// baseline (speedup 1.0000x reference)
#include <cuda_runtime.h>

// SpikingVestibular — HBM-streaming kernel, round 2.
// 2 batch elements per thread -> 48B/thread blocks, 16B-aligned -> float4 I/O.
// __ldcs/__stcs streaming hints: all bulk data is touched exactly once.

__global__ __launch_bounds__(256)
void sv_kernel2(const float* __restrict__ speed_p,
                const float* __restrict__ turn_p,
                const float* __restrict__ pt_p,
                const float* __restrict__ ps_p,
                const float* __restrict__ noise,
                const float* __restrict__ v0,
                const float* __restrict__ u0,
                const float* __restrict__ r0,
                float* __restrict__ out,
                int B)
{
    int t = blockIdx.x * blockDim.x + threadIdx.x;
    int b0 = t * 2;
    if (b0 >= B) return;

    size_t stepStride = (size_t)B * 6;

    if (b0 + 1 < B) {
        // ---- pair path: elements b0, b0+1 ; base is 48B-aligned ----
        float2 sp2 = __ldcs(reinterpret_cast<const float2*>(speed_p + b0));
        float2 tr2 = __ldcs(reinterpret_cast<const float2*>(turn_p + b0));
        float2 pt2 = __ldcs(reinterpret_cast<const float2*>(pt_p + b0));
        float2 ps2 = __ldcs(reinterpret_cast<const float2*>(ps_p + b0));

        float sp[2] = {sp2.x, sp2.y};
        float tr[2] = {tr2.x, tr2.y};
        float tilt[2];
        float I[12];
        #pragma unroll
        for (int e = 0; e < 2; e++) {
            tilt[e] = fminf(1.0f, fabsf(tr[e]) * sp[e] * 0.5f);
            I[6*e+0] = fmaxf(0.0f,  tr[e]) * 10.0f;
            I[6*e+1] = fmaxf(0.0f, -tr[e]) * 10.0f;
            I[6*e+2] = sp[e] * 5.0f;
            I[6*e+3] = fmaxf(0.0f, -sp[e] + 0.5f) * 5.0f;
            I[6*e+4] = tilt[e] * 8.0f;
            I[6*e+5] = tilt[e] * 8.0f;
        }

        size_t base = (size_t)b0 * 6;

        float v[12], u[12], r[12];
        {
            const float4* v4 = reinterpret_cast<const float4*>(v0 + base);
            const float4* u4 = reinterpret_cast<const float4*>(u0 + base);
            const float4* r4 = reinterpret_cast<const float4*>(r0 + base);
            #pragma unroll
            for (int i = 0; i < 3; i++) {
                float4 a = __ldcs(v4 + i);
                v[4*i] = a.x; v[4*i+1] = a.y; v[4*i+2] = a.z; v[4*i+3] = a.w;
                float4 c = __ldcs(u4 + i);
                u[4*i] = c.x; u[4*i+1] = c.y; u[4*i+2] = c.z; u[4*i+3] = c.w;
                float4 d = __ldcs(r4 + i);
                r[4*i] = d.x; r[4*i+1] = d.y; r[4*i+2] = d.z; r[4*i+3] = d.w;
            }
        }

        #pragma unroll
        for (int s = 0; s < 10; s++) {
            float nz[12];
            {
                const float4* nz4 = reinterpret_cast<const float4*>(
                    noise + (size_t)s * stepStride + base);
                #pragma unroll
                for (int i = 0; i < 3; i++) {
                    float4 a = __ldcs(nz4 + i);
                    nz[4*i] = a.x; nz[4*i+1] = a.y; nz[4*i+2] = a.z; nz[4*i+3] = a.w;
                }
            }
            #pragma unroll
            for (int n = 0; n < 12; n++) {
                float i_tot = I[n] + nz[n] * 0.3f - 1.0f;
                float vv = v[n];
                vv = vv + (0.04f * vv * vv + 5.0f * vv + 140.0f - u[n] + i_tot);
                float uu = u[n] + 0.02f * (0.2f * vv - u[n]);
                bool fired = (vv >= 30.0f);
                float spk = fired ? 1.0f : 0.0f;
                if (fired) vv = -65.0f;
                uu += spk * 8.0f;
                r[n] = r[n] * 0.9f + spk * 0.1f;
                v[n] = vv;
                u[n] = uu;
            }
        }

        float pt_[2] = {pt2.x, pt2.y};
        float ps_[2] = {ps2.x, ps2.y};
        float res[12];
        #pragma unroll
        for (int e = 0; e < 2; e++) {
            float rate_mean = (r[6*e+0] + r[6*e+1] + r[6*e+2] +
                               r[6*e+3] + r[6*e+4] + r[6*e+5]) * (1.0f / 6.0f);
            float vb0 = 0.0f, vb1 = 0.0f, va0 = 0.0f, va1 = 0.0f;
            #pragma unroll
            for (int s = 0; s < 8; s++) {
                vb0 += 0.5f * (tr[e]  - vb0);
                vb1 += 0.5f * (sp[e]  - vb1);
                va0 += 0.5f * (pt_[e] - va0);
                va1 += 0.5f * (ps_[e] - va1);
            }
            float pe0 = vb0 - va0;
            float pe1 = vb1 - va1;
            float p0 = 1.0f / (1.0f + pe0 * pe0);
            float p1 = 1.0f / (1.0f + pe1 * pe1);
            float fe = 0.5f * (p0 * pe0 * pe0 + p1 * pe1 * pe1);
            float pe_w = 0.7f * pe0 + 0.3f * pe1;
            float prec_mean = 0.5f * (p0 + p1);
            float postural = -prec_mean * pe_w * 0.3f;
            res[6*e+0] = tilt[e];
            res[6*e+1] = rate_mean;
            res[6*e+2] = postural;
            res[6*e+3] = pe_w;
            res[6*e+4] = prec_mean;
            res[6*e+5] = fe;
        }

        float4* o4 = reinterpret_cast<float4*>(out + base);
        __stcs(o4 + 0, make_float4(res[0], res[1], res[2],  res[3]));
        __stcs(o4 + 1, make_float4(res[4], res[5], res[6],  res[7]));
        __stcs(o4 + 2, make_float4(res[8], res[9], res[10], res[11]));
    } else {
        // ---- tail path: single element (scalar/float2, rarely taken) ----
        int b = b0;
        float speed = speed_p[b];
        float tr    = turn_p[b];
        float tilt = fminf(1.0f, fabsf(tr) * speed * 0.5f);
        float I[6];
        I[0] = fmaxf(0.0f,  tr) * 10.0f;
        I[1] = fmaxf(0.0f, -tr) * 10.0f;
        I[2] = speed * 5.0f;
        I[3] = fmaxf(0.0f, -speed + 0.5f) * 5.0f;
        I[4] = tilt * 8.0f;
        I[5] = tilt * 8.0f;

        size_t base = (size_t)b * 6;
        float v[6], u[6], r[6];
        #pragma unroll
        for (int n = 0; n < 6; n++) {
            v[n] = v0[base + n];
            u[n] = u0[base + n];
            r[n] = r0[base + n];
        }
        #pragma unroll
        for (int s = 0; s < 10; s++) {
            #pragma unroll
            for (int n = 0; n < 6; n++) {
                float nz = noise[(size_t)s * stepStride + base + n];
                float i_tot = I[n] + nz * 0.3f - 1.0f;
                float vv = v[n];
                vv = vv + (0.04f * vv * vv + 5.0f * vv + 140.0f - u[n] + i_tot);
                float uu = u[n] + 0.02f * (0.2f * vv - u[n]);
                bool fired = (vv >= 30.0f);
                float spk = fired ? 1.0f : 0.0f;
                if (fired) vv = -65.0f;
                uu += spk * 8.0f;
                r[n] = r[n] * 0.9f + spk * 0.1f;
                v[n] = vv;
                u[n] = uu;
            }
        }
        float rate_mean = (r[0]+r[1]+r[2]+r[3]+r[4]+r[5]) * (1.0f/6.0f);
        float pt = pt_p[b], ps = ps_p[b];
        float vb0 = 0.0f, vb1 = 0.0f, va0 = 0.0f, va1 = 0.0f;
        #pragma unroll
        for (int s = 0; s < 8; s++) {
            vb0 += 0.5f * (tr    - vb0);
            vb1 += 0.5f * (speed - vb1);
            va0 += 0.5f * (pt    - va0);
            va1 += 0.5f * (ps    - va1);
        }
        float pe0 = vb0 - va0;
        float pe1 = vb1 - va1;
        float p0 = 1.0f / (1.0f + pe0 * pe0);
        float p1 = 1.0f / (1.0f + pe1 * pe1);
        float fe = 0.5f * (p0 * pe0 * pe0 + p1 * pe1 * pe1);
        float pe_w = 0.7f * pe0 + 0.3f * pe1;
        float prec_mean = 0.5f * (p0 + p1);
        float postural = -prec_mean * pe_w * 0.3f;
        out[base + 0] = tilt;
        out[base + 1] = rate_mean;
        out[base + 2] = postural;
        out[base + 3] = pe_w;
        out[base + 4] = prec_mean;
        out[base + 5] = fe;
    }
}

extern "C" void kernel_launch(void* const* d_in, const int* in_sizes, int n_in,
                              void* d_out, int out_size) {
    // metadata order: heading, speed, turn_rate, predicted_turn,
    //                 predicted_speed, noise, v0, u0, rate0
    const float* speed = (const float*)d_in[1];
    const float* turn  = (const float*)d_in[2];
    const float* pt    = (const float*)d_in[3];
    const float* ps    = (const float*)d_in[4];
    const float* noise = (const float*)d_in[5];
    const float* v0    = (const float*)d_in[6];
    const float* u0    = (const float*)d_in[7];
    const float* r0    = (const float*)d_in[8];

    int B = in_sizes[0];
    int nPairs = (B + 1) / 2;
    int threads = 256;
    int blocks = (nPairs + threads - 1) / threads;
    sv_kernel2<<<blocks, threads>>>(speed, turn, pt, ps, noise, v0, u0, r0,
                                    (float*)d_out, B);
}

// round 4
// speedup vs baseline: 1.0534x; 1.0534x over previous
#include <cuda_runtime.h>

// SpikingVestibular — round 3: R1 structure (1 element/thread, float2 I/O)
// with register squeeze for occupancy. __launch_bounds__(256,6) caps regs at
// ~42 -> 6 blocks/SM (75% occ) vs R1's 5 (62.5%). DRAM utilization tracked
// occupancy across R1/R2; this buys bytes-in-flight where R2 lost them.

__global__ __launch_bounds__(256, 6)
void sv_kernel3(const float* __restrict__ speed_p,
                const float* __restrict__ turn_p,
                const float* __restrict__ pt_p,
                const float* __restrict__ ps_p,
                const float* __restrict__ noise,
                const float* __restrict__ v0,
                const float* __restrict__ u0,
                const float* __restrict__ r0,
                float* __restrict__ out,
                int B)
{
    int b = blockIdx.x * blockDim.x + threadIdx.x;
    if (b >= B) return;

    float speed = speed_p[b];
    float tr    = turn_p[b];

    // tilt recomputed after the loop; only I[] (with I[4]==I[5] CSE'd) lives
    // through the hot region.
    float tiltI = fminf(1.0f, fabsf(tr) * speed * 0.5f);

    float I[6];
    I[0] = fmaxf(0.0f,  tr) * 10.0f;
    I[1] = fmaxf(0.0f, -tr) * 10.0f;
    I[2] = speed * 5.0f;
    I[3] = fmaxf(0.0f, -speed + 0.5f) * 5.0f;
    I[4] = tiltI * 8.0f;
    I[5] = I[4];

    size_t base = (size_t)b * 6;
    size_t stepStride = (size_t)B * 6;

    float v[6], u[6], r[6];
    {
        const float2* v2 = reinterpret_cast<const float2*>(v0 + base);
        const float2* u2 = reinterpret_cast<const float2*>(u0 + base);
        const float2* r2 = reinterpret_cast<const float2*>(r0 + base);
        #pragma unroll
        for (int i = 0; i < 3; i++) {
            float2 a = __ldcs(v2 + i); v[2*i] = a.x; v[2*i+1] = a.y;
            float2 c = __ldcs(u2 + i); u[2*i] = c.x; u[2*i+1] = c.y;
            float2 d = __ldcs(r2 + i); r[2*i] = d.x; r[2*i+1] = d.y;
        }
    }

    const float2* nzp = reinterpret_cast<const float2*>(noise + base);

    #pragma unroll
    for (int s = 0; s < 10; s++) {
        float nz[6];
        {
            const float2* nz2 = reinterpret_cast<const float2*>(
                reinterpret_cast<const float*>(nzp) + (size_t)s * stepStride);
            #pragma unroll
            for (int i = 0; i < 3; i++) {
                float2 a = __ldcs(nz2 + i);
                nz[2*i] = a.x; nz[2*i+1] = a.y;
            }
        }
        #pragma unroll
        for (int n = 0; n < 6; n++) {
            float i_tot = I[n] + nz[n] * 0.3f - 1.0f;
            float vv = v[n];
            vv = vv + (0.04f * vv * vv + 5.0f * vv + 140.0f - u[n] + i_tot);
            float uu = u[n] + 0.02f * (0.2f * vv - u[n]);
            bool fired = (vv >= 30.0f);
            float spk = fired ? 1.0f : 0.0f;
            if (fired) vv = -65.0f;
            uu += spk * 8.0f;
            r[n] = r[n] * 0.9f + spk * 0.1f;
            v[n] = vv;
            u[n] = uu;
        }
    }

    float rate_mean = (r[0] + r[1] + r[2] + r[3] + r[4] + r[5]) * (1.0f / 6.0f);

    // Post-loop: reload-free scalar tail. pt/ps loaded only now (L2-resident
    // small arrays; keeps them out of the hot region's register budget).
    float tilt = fminf(1.0f, fabsf(tr) * speed * 0.5f);
    float pt = pt_p[b];
    float ps = ps_p[b];
    float vb0 = 0.0f, vb1 = 0.0f, va0 = 0.0f, va1 = 0.0f;
    #pragma unroll
    for (int s = 0; s < 8; s++) {
        vb0 += 0.5f * (tr    - vb0);
        vb1 += 0.5f * (speed - vb1);
        va0 += 0.5f * (pt    - va0);
        va1 += 0.5f * (ps    - va1);
    }
    float pe0 = vb0 - va0;
    float pe1 = vb1 - va1;
    float p0 = 1.0f / (1.0f + pe0 * pe0);
    float p1 = 1.0f / (1.0f + pe1 * pe1);
    float fe = 0.5f * (p0 * pe0 * pe0 + p1 * pe1 * pe1);
    float pe_w = 0.7f * pe0 + 0.3f * pe1;
    float prec_mean = 0.5f * (p0 + p1);
    float postural = -prec_mean * pe_w * 0.3f;

    float2* o2 = reinterpret_cast<float2*>(out + base);
    __stcs(o2 + 0, make_float2(tilt, rate_mean));
    __stcs(o2 + 1, make_float2(postural, pe_w));
    __stcs(o2 + 2, make_float2(prec_mean, fe));
}

extern "C" void kernel_launch(void* const* d_in, const int* in_sizes, int n_in,
                              void* d_out, int out_size) {
    // metadata order: heading, speed, turn_rate, predicted_turn,
    //                 predicted_speed, noise, v0, u0, rate0
    const float* speed = (const float*)d_in[1];
    const float* turn  = (const float*)d_in[2];
    const float* pt    = (const float*)d_in[3];
    const float* ps    = (const float*)d_in[4];
    const float* noise = (const float*)d_in[5];
    const float* v0    = (const float*)d_in[6];
    const float* u0    = (const float*)d_in[7];
    const float* r0    = (const float*)d_in[8];

    int B = in_sizes[0];
    int threads = 256;
    int blocks = (B + threads - 1) / threads;
    sv_kernel3<<<blocks, threads>>>(speed, turn, pt, ps, noise, v0, u0, r0,
                                    (float*)d_out, B);
}